// round 12
// baseline (speedup 1.0000x reference)
#include <cuda_runtime.h>
#include <cuda_bf16.h>

#define B_DIM 32
#define T_DIM 1024
#define J_DIM 52
#define NBT (B_DIM * T_DIM)
#define SPLIT 8            // threads per (b,t): one per depth-3 subtree root (nodes 7..14)
#define BT_PER_BLK 16      // (b,t) rows per block
#define THREADS (BT_PER_BLK * SPLIT)   // 128
#define IN_FLOATS (J_DIM * 6)          // 312 floats per bt (global layout)
#define OUT_FLOATS (J_DIM * 3)         // 156 floats per bt (global layout)
#define IN_STRIDE 316                  // padded smem stride (mod 32 = 28: btl groups on distinct banks)
#define OUT_STRIDE 164                 // padded smem stride (mod 32 = 4)

// rot6d -> 3x3 rotation matrix L (row-major, columns = b1,b2,b3) from smem.
// Two independent rsqrtf's (w = n1*a2 - (a1.a2)*a1 is parallel to Gram-Schmidt b2).
__device__ __forceinline__ void conv_L(const float* __restrict__ r6, int j, float (&L)[9]) {
    const float2* v = reinterpret_cast<const float2*>(r6 + j * 6);  // 8B-aligned
    float2 q0 = v[0], q1 = v[1], q2 = v[2];
    float a1x = q0.x, a1y = q0.y, a1z = q1.x;
    float a2x = q1.y, a2y = q2.x, a2z = q2.y;

    float n1 = a1x * a1x + a1y * a1y + a1z * a1z;
    float d0 = a1x * a2x + a1y * a2y + a1z * a2z;

    float wx = n1 * a2x - d0 * a1x;
    float wy = n1 * a2y - d0 * a1y;
    float wz = n1 * a2z - d0 * a1z;
    float n2 = wx * wx + wy * wy + wz * wz;

    float i1 = rsqrtf(fmaxf(n1, 1e-24f));
    float i2 = rsqrtf(fmaxf(n2, 1e-40f));

    float b1x = a1x * i1, b1y = a1y * i1, b1z = a1z * i1;
    float b2x = wx * i2,  b2y = wy * i2,  b2z = wz * i2;

    float b3x = b1y * b2z - b1z * b2y;
    float b3y = b1z * b2x - b1x * b2z;
    float b3z = b1x * b2y - b1y * b2x;

    L[0] = b1x; L[1] = b2x; L[2] = b3x;
    L[3] = b1y; L[4] = b2y; L[5] = b3y;
    L[6] = b1z; L[7] = b2z; L[8] = b3z;
}

// lr = L @ rest[j]
__device__ __forceinline__ void conv_lr(const float (&L)[9], const float* __restrict__ rest,
                                        int j, float (&lr)[3]) {
    float rx = __ldg(rest + j * 3 + 0);
    float ry = __ldg(rest + j * 3 + 1);
    float rz = __ldg(rest + j * 3 + 2);
    lr[0] = L[0] * rx + L[1] * ry + L[2] * rz;
    lr[1] = L[3] * rx + L[4] * ry + L[5] * rz;
    lr[2] = L[6] * rx + L[7] * ry + L[8] * rz;
}

// pos_out = pos_in + gR @ lr   (9 fma, short dependency)
__device__ __forceinline__ void apply_pos(const float (&gR)[9], const float (&lr)[3],
                                          const float (&pin)[3], float (&pout)[3]) {
    pout[0] = pin[0] + gR[0] * lr[0] + gR[1] * lr[1] + gR[2] * lr[2];
    pout[1] = pin[1] + gR[3] * lr[0] + gR[4] * lr[1] + gR[5] * lr[2];
    pout[2] = pin[2] + gR[6] * lr[0] + gR[7] * lr[1] + gR[8] * lr[2];
}

// gR = gR @ L (in place)
__device__ __forceinline__ void advance_gR(float (&gR)[9], const float (&L)[9]) {
    #pragma unroll
    for (int i = 0; i < 3; i++) {
        float p0 = gR[i * 3 + 0];
        float p1 = gR[i * 3 + 1];
        float p2 = gR[i * 3 + 2];
        gR[i * 3 + 0] = p0 * L[0] + p1 * L[3] + p2 * L[6];
        gR[i * 3 + 1] = p0 * L[1] + p1 * L[4] + p2 * L[7];
        gR[i * 3 + 2] = p0 * L[2] + p1 * L[5] + p2 * L[8];
    }
}

// gRc = gRp @ L (out of place)
__device__ __forceinline__ void mul_gR(const float (&gRp)[9], const float (&L)[9], float (&gRc)[9]) {
    #pragma unroll
    for (int i = 0; i < 3; i++) {
        float p0 = gRp[i * 3 + 0];
        float p1 = gRp[i * 3 + 1];
        float p2 = gRp[i * 3 + 2];
        gRc[i * 3 + 0] = p0 * L[0] + p1 * L[3] + p2 * L[6];
        gRc[i * 3 + 1] = p0 * L[1] + p1 * L[4] + p2 * L[7];
        gRc[i * 3 + 2] = p0 * L[2] + p1 * L[5] + p2 * L[8];
    }
}

// Leaf: position only (conv inline; independent of other leaves -> tail ILP).
__device__ __forceinline__ void leaf_node(int j,
                                          const float* __restrict__ r6,
                                          const float* __restrict__ rest,
                                          const float (&gR)[9], const float (&pos)[3],
                                          float* __restrict__ o) {
    float L[9], lr[3];
    conv_L(r6, j, L);
    conv_lr(L, rest, j, lr);
    float p[3];
    apply_pos(gR, lr, pos, p);
    o[j * 3 + 0] = p[0];
    o[j * 3 + 1] = p[1];
    o[j * 3 + 2] = p[2];
}

__global__ void __launch_bounds__(THREADS)
fk_kernel(const float* __restrict__ rot6d,
          const float* __restrict__ trans,
          const float* __restrict__ yaw,
          const float* __restrict__ rest,
          float* __restrict__ out) {
    __shared__ float s_in[BT_PER_BLK * IN_STRIDE];    // 20224 B
    __shared__ float s_out[BT_PER_BLK * OUT_STRIDE];  // 10496 B

    int tid = threadIdx.x;
    int blk = blockIdx.x;

    // ---- Phase 1: coalesced float4 load into padded smem rows ----
    {
        const float4* gsrc = reinterpret_cast<const float4*>(
            rot6d + (size_t)blk * BT_PER_BLK * IN_FLOATS);
        const int NCHUNK = IN_FLOATS / 4;  // 78
        #pragma unroll
        for (int i = tid; i < BT_PER_BLK * NCHUNK; i += THREADS) {
            int row = i / NCHUNK;
            int c = i - row * NCHUNK;
            *reinterpret_cast<float4*>(s_in + row * IN_STRIDE + c * 4) = gsrc[i];
        }
    }
    __syncthreads();

    // ---- Phase 2: compute (8 threads per bt; thread s owns subtree at 7+s) ----
    {
        int bt_local = tid >> 3;
        int s = tid & 7;
        int bt = blk * BT_PER_BLK + bt_local;

        const float* r6 = s_in + bt_local * IN_STRIDE;
        float* o = s_out + bt_local * OUT_STRIDE;

        int n1 = 1 + (s >> 2);
        int n2 = 3 + (s >> 1);
        int A  = 7 + s;
        int Bn = 15 + 2 * s;
        int Cn = Bn + 1;

        // ---- front-load ALL chain-node conversions (mutually independent) ----
        float L0[9], L1[9], L2[9], LA[9], LB[9], LC[9];
        conv_L(r6, 0, L0);
        conv_L(r6, n1, L1);
        conv_L(r6, n2, L2);
        conv_L(r6, A,  LA);
        conv_L(r6, Bn, LB);
        conv_L(r6, Cn, LC);

        float lr1[3], lr2[3], lrA[3], lrB[3], lrC[3];
        conv_lr(L1, rest, n1, lr1);
        conv_lr(L2, rest, n2, lr2);
        conv_lr(LA, rest, A,  lrA);
        conv_lr(LB, rest, Bn, lrB);
        conv_lr(LC, rest, Cn, lrC);

        // root state
        float sy, cy;
        __sincosf(yaw[bt], &sy, &cy);
        float gR[9];
        gR[0] = cy * L0[0] + sy * L0[6];
        gR[1] = cy * L0[1] + sy * L0[7];
        gR[2] = cy * L0[2] + sy * L0[8];
        gR[3] = L0[3];
        gR[4] = L0[4];
        gR[5] = L0[5];
        gR[6] = cy * L0[6] - sy * L0[0];
        gR[7] = cy * L0[7] - sy * L0[1];
        gR[8] = cy * L0[8] - sy * L0[2];

        float pos[3];
        pos[0] = trans[bt * 3 + 0];
        pos[1] = trans[bt * 3 + 1];
        pos[2] = trans[bt * 3 + 2];
        if (s == 0) { o[0] = pos[0]; o[1] = pos[1]; o[2] = pos[2]; }

        // ---- short serial FMA chain (conversions already in registers) ----
        apply_pos(gR, lr1, pos, pos);
        if ((s & 3) == 0) { o[n1*3+0] = pos[0]; o[n1*3+1] = pos[1]; o[n1*3+2] = pos[2]; }
        advance_gR(gR, L1);

        apply_pos(gR, lr2, pos, pos);
        if ((s & 1) == 0) { o[n2*3+0] = pos[0]; o[n2*3+1] = pos[1]; o[n2*3+2] = pos[2]; }
        advance_gR(gR, L2);

        apply_pos(gR, lrA, pos, pos);
        o[A*3+0] = pos[0]; o[A*3+1] = pos[1]; o[A*3+2] = pos[2];
        advance_gR(gR, LA);

        // ---- branches B and C (independent) ----
        float posB[3], posC[3], gRB[9], gRC[9];
        apply_pos(gR, lrB, pos, posB);
        apply_pos(gR, lrC, pos, posC);
        o[Bn*3+0] = posB[0]; o[Bn*3+1] = posB[1]; o[Bn*3+2] = posB[2];
        o[Cn*3+0] = posC[0]; o[Cn*3+1] = posC[1]; o[Cn*3+2] = posC[2];
        mul_gR(gR, LB, gRB);
        mul_gR(gR, LC, gRC);

        // ---- depth-5 leaves (up to 4, independent) ----
        int l1 = 31 + 4 * s;   // child of B
        int l2 = l1 + 1;
        int l3 = l1 + 2;       // child of C
        int l4 = l1 + 3;
        if (l1 < J_DIM) leaf_node(l1, r6, rest, gRB, posB, o);
        if (l2 < J_DIM) leaf_node(l2, r6, rest, gRB, posB, o);
        if (l3 < J_DIM) leaf_node(l3, r6, rest, gRC, posC, o);
        if (l4 < J_DIM) leaf_node(l4, r6, rest, gRC, posC, o);
    }
    __syncthreads();

    // ---- Phase 3: coalesced float4 store from padded smem rows ----
    {
        float4* gdst = reinterpret_cast<float4*>(
            out + (size_t)blk * BT_PER_BLK * OUT_FLOATS);
        const int NCHUNK = OUT_FLOATS / 4;  // 39
        #pragma unroll
        for (int i = tid; i < BT_PER_BLK * NCHUNK; i += THREADS) {
            int row = i / NCHUNK;
            int c = i - row * NCHUNK;
            gdst[i] = *reinterpret_cast<const float4*>(s_out + row * OUT_STRIDE + c * 4);
        }
    }
}

extern "C" void kernel_launch(void* const* d_in, const int* in_sizes, int n_in,
                              void* d_out, int out_size) {
    const float* rot6d = (const float*)d_in[0];
    const float* trans = (const float*)d_in[1];
    const float* yaw   = (const float*)d_in[2];
    // d_in[3] = parents (int64) — binary-heap tree is fixed at compile time.
    const float* rest  = (const float*)d_in[4];
    float* out = (float*)d_out;

    dim3 block(THREADS);
    dim3 grid(NBT / BT_PER_BLK);   // 2048 blocks, exact
    fk_kernel<<<grid, block>>>(rot6d, trans, yaw, rest, out);
}